// round 6
// baseline (speedup 1.0000x reference)
#include <cuda_runtime.h>
#include <cuda_fp16.h>
#include <cstdint>

#define CDIM   2048
#define EDIM   64
#define NTOT   128          // 64 route + 64 noise outputs fused in N
#define TOPK   8
#define MT     64           // tokens per CTA
#define KC     32           // K per chunk
#define NCHUNK (CDIM / KC)  // 64

// operand scaling to keep fp16 residuals out of subnormal range
#define XSCALE   16.0f
#define WSCALE   64.0f
#define DESCALE  (1.0f / (XSCALE * WSCALE))

// smem tile rows: 32 halves (64B) padded to 80B (conflict-free ldmatrix)
#define AROW        80
#define A_TILE_B    (MT * AROW)          // 5120 B  (A hi or lo)
#define B_TILE_B    (NTOT * AROW)        // 10240 B (B hi or lo)
#define STAGE_B     (2 * A_TILE_B + 2 * B_TILE_B)   // 30720 B
#define SMEM_DYN    (2 * STAGE_B)        // 61440 B (reused as Ls in epilogue)
#define LS_STRIDE   129                  // 64*129*4 = 33024 B < SMEM_DYN

// precomputed W split (prep kernel): [NTOT][CDIM] halves, scaled by WSCALE
__device__ __half Whi_g[NTOT * CDIM];
__device__ __half Wlo_g[NTOT * CDIM];

static __device__ __forceinline__ uint32_t smem_u32(const void* p) {
    uint32_t a;
    asm("{ .reg .u64 t; cvta.to.shared.u64 t, %1; cvt.u32.u64 %0, t; }" : "=r"(a) : "l"(p));
    return a;
}
static __device__ __forceinline__ void ldm_x4(uint32_t& r0, uint32_t& r1, uint32_t& r2,
                                              uint32_t& r3, uint32_t addr) {
    asm volatile("ldmatrix.sync.aligned.m8n8.x4.shared.b16 {%0,%1,%2,%3}, [%4];"
                 : "=r"(r0), "=r"(r1), "=r"(r2), "=r"(r3) : "r"(addr));
}
static __device__ __forceinline__ void mma16816(float* c, const uint32_t* a,
                                                const uint32_t* b) {
    asm volatile(
        "mma.sync.aligned.m16n8k16.row.col.f32.f16.f16.f32 "
        "{%0,%1,%2,%3}, {%4,%5,%6,%7}, {%8,%9}, {%0,%1,%2,%3};"
        : "+f"(c[0]), "+f"(c[1]), "+f"(c[2]), "+f"(c[3])
        : "r"(a[0]), "r"(a[1]), "r"(a[2]), "r"(a[3]), "r"(b[0]), "r"(b[1]));
}
static __device__ __forceinline__ uint32_t pack2h(__half a, __half b) {
    __half2 h = __halves2half2(a, b);
    return *reinterpret_cast<uint32_t*>(&h);
}
// Scale, then split into hi/lo fp16 quads and store 8B each.
static __device__ __forceinline__ void cvt_store(char* hi, char* lo, uint32_t off,
                                                 float4 v, float scale) {
    v.x *= scale; v.y *= scale; v.z *= scale; v.w *= scale;
    __half h0 = __float2half_rn(v.x), h1 = __float2half_rn(v.y);
    __half h2 = __float2half_rn(v.z), h3 = __float2half_rn(v.w);
    float r0 = v.x - __half2float(h0), r1 = v.y - __half2float(h1);
    float r2 = v.z - __half2float(h2), r3 = v.w - __half2float(h3);
    uint2 ph = make_uint2(pack2h(h0, h1), pack2h(h2, h3));
    uint2 pl = make_uint2(pack2h(__float2half_rn(r0), __float2half_rn(r1)),
                          pack2h(__float2half_rn(r2), __float2half_rn(r3)));
    *(uint2*)(hi + off) = ph;
    *(uint2*)(lo + off) = pl;
}

// ---- prep: split W (route||noise) into scaled hi/lo fp16 globals ----
__global__ void prep_w_kernel(const float* __restrict__ wr, const float* __restrict__ wn) {
    const int stride = gridDim.x * blockDim.x;
    for (int e = blockIdx.x * blockDim.x + threadIdx.x; e < NTOT * CDIM; e += stride) {
        const int row = e >> 11, col = e & (CDIM - 1);
        float v = (row < EDIM ? wr[row * CDIM + col] : wn[(row - EDIM) * CDIM + col]) * WSCALE;
        __half h = __float2half_rn(v);
        Whi_g[e] = h;
        Wlo_g[e] = __float2half_rn(v - __half2float(h));
    }
}

__global__ __launch_bounds__(256, 2)
void router_mma_kernel(
    const float* __restrict__ x, const float* __restrict__ noise,
    float* __restrict__ out_router, float* __restrict__ out_indices, int write_indices)
{
    extern __shared__ __align__(16) char smem[];
    __shared__ float s_max[MT];
    __shared__ float s_inv[MT];
    __shared__ unsigned long long s_msk[MT];

    const uint32_t sb = smem_u32(smem);
    const int tid = threadIdx.x;
    const int wid = tid >> 5, lane = tid & 31;
    const int wr_ = wid >> 1;            // warp row: tokens [16*wr_, +16)
    const int wc_ = wid & 1;             // warp col: outputs [64*wc_, +64)
    const int tokBase = blockIdx.x * MT;

    // A fill mapping: idx = tid + 256*it (it 0..1) -> row = idx>>3 (0..63), q = idx&7
    const int af_row = tid >> 3;
    const int af_q   = tid & 7;
    // B fill mapping: idx = tid + 256*it (it 0..1) -> row = idx>>2 (0..127), q = idx&3
    const int bf_row = tid >> 2;
    const int bf_q   = tid & 3;

    // ldmatrix lane-address components
    const int j = lane >> 3, rr = lane & 7;
    const int a_off0 = (16 * wr_ + (j & 1) * 8 + rr) * AROW + (j >> 1) * 16;   // + ks*32
    const int b_off0 = (64 * wc_ + (j >> 1) * 8 + rr) * AROW + (j & 1) * 16;   // + p*16*80 + ks*32

    float acc[8][4];
#pragma unroll
    for (int nt = 0; nt < 8; ++nt)
#pragma unroll
        for (int k = 0; k < 4; ++k) acc[nt][k] = 0.0f;

    // ---- prologue: chunk 0 -> stage 0 ----
    float4 areg[2];
    uint4  bh_reg[2], bl_reg[2];
#pragma unroll
    for (int it = 0; it < 2; ++it) {
        areg[it] = *(const float4*)(x + (size_t)(tokBase + af_row + it * 32) * CDIM + af_q * 4);
        const size_t wi = (size_t)(bf_row + it * 64) * CDIM + bf_q * 8;
        bh_reg[it] = *(const uint4*)(Whi_g + wi);
        bl_reg[it] = *(const uint4*)(Wlo_g + wi);
    }
    {
        char* Ah = smem;                       char* Al = smem + A_TILE_B;
        char* Bh = smem + 2 * A_TILE_B;        char* Bl = Bh + B_TILE_B;
#pragma unroll
        for (int it = 0; it < 2; ++it) {
            cvt_store(Ah, Al, (uint32_t)(af_row + it * 32) * AROW + af_q * 8, areg[it], XSCALE);
            const uint32_t bo = (uint32_t)(bf_row + it * 64) * AROW + bf_q * 16;
            *(uint4*)(Bh + bo) = bh_reg[it];
            *(uint4*)(Bl + bo) = bl_reg[it];
        }
    }
    __syncthreads();

    // ---- mainloop: prefetch(c+1) || compute(c) || publish(c+1), one sync ----
    for (int c = 0; c < NCHUNK; ++c) {
        const int s = c & 1;
        const int has_next = (c + 1 < NCHUNK);
        if (has_next) {
            const int k0 = (c + 1) * KC;
#pragma unroll
            for (int it = 0; it < 2; ++it) {
                areg[it] = *(const float4*)(x + (size_t)(tokBase + af_row + it * 32) * CDIM
                                            + k0 + af_q * 4);
                const size_t wi = (size_t)(bf_row + it * 64) * CDIM + k0 + bf_q * 8;
                bh_reg[it] = *(const uint4*)(Whi_g + wi);
                bl_reg[it] = *(const uint4*)(Wlo_g + wi);
            }
        }

        // compute chunk c from stage s
        const uint32_t ah_b = sb + s * STAGE_B;
        const uint32_t al_b = ah_b + A_TILE_B;
        const uint32_t bh_b = ah_b + 2 * A_TILE_B;
        const uint32_t bl_b = bh_b + B_TILE_B;
#pragma unroll
        for (int ks = 0; ks < 2; ++ks) {
            uint32_t a_hi[4], a_lo[4];
            ldm_x4(a_hi[0], a_hi[1], a_hi[2], a_hi[3], ah_b + a_off0 + ks * 32);
            ldm_x4(a_lo[0], a_lo[1], a_lo[2], a_lo[3], al_b + a_off0 + ks * 32);
            uint32_t b_hi[8][2], b_lo[8][2];
#pragma unroll
            for (int p = 0; p < 4; ++p) {
                const uint32_t bo = b_off0 + p * (16 * AROW) + ks * 32;
                ldm_x4(b_hi[2 * p][0], b_hi[2 * p][1], b_hi[2 * p + 1][0], b_hi[2 * p + 1][1],
                       bh_b + bo);
                ldm_x4(b_lo[2 * p][0], b_lo[2 * p][1], b_lo[2 * p + 1][0], b_lo[2 * p + 1][1],
                       bl_b + bo);
            }
#pragma unroll
            for (int nt = 0; nt < 8; ++nt) {
                mma16816(acc[nt], a_hi, b_hi[nt]);
                mma16816(acc[nt], a_hi, b_lo[nt]);
                mma16816(acc[nt], a_lo, b_hi[nt]);
            }
        }

        // publish chunk c+1 into the other stage
        if (has_next) {
            char* Ah = smem + (1 - s) * STAGE_B;
            char* Al = Ah + A_TILE_B;
            char* Bh = Ah + 2 * A_TILE_B;
            char* Bl = Bh + B_TILE_B;
#pragma unroll
            for (int it = 0; it < 2; ++it) {
                cvt_store(Ah, Al, (uint32_t)(af_row + it * 32) * AROW + af_q * 8,
                          areg[it], XSCALE);
                const uint32_t bo = (uint32_t)(bf_row + it * 64) * AROW + bf_q * 16;
                *(uint4*)(Bh + bo) = bh_reg[it];
                *(uint4*)(Bl + bo) = bl_reg[it];
            }
        }
        __syncthreads();
    }

    // --- accumulators -> Ls[token][output] (smem reuse, descaled) ---
    float* Ls = (float*)smem;
    {
        const int r0 = 16 * wr_ + (lane >> 2);
        const int c0 = 64 * wc_ + 2 * (lane & 3);
#pragma unroll
        for (int nt = 0; nt < 8; ++nt) {
            const int col = c0 + 8 * nt;
            Ls[r0 * LS_STRIDE + col]           = acc[nt][0] * DESCALE;
            Ls[r0 * LS_STRIDE + col + 1]       = acc[nt][1] * DESCALE;
            Ls[(r0 + 8) * LS_STRIDE + col]     = acc[nt][2] * DESCALE;
            Ls[(r0 + 8) * LS_STRIDE + col + 1] = acc[nt][3] * DESCALE;
        }
    }
    __syncthreads();

    // --- noisy = logit + noise * softplus(noise_logit) ---
    for (int i = tid; i < MT * EDIM; i += 256) {
        const int t = i >> 6, e = i & 63;
        float l  = Ls[t * LS_STRIDE + e];
        float nl = Ls[t * LS_STRIDE + EDIM + e];
        float nz = noise[(size_t)(tokBase + t) * EDIM + e];
        float sp = fmaxf(nl, 0.0f) + log1pf(expf(-fabsf(nl)));
        Ls[t * LS_STRIDE + e] = fmaf(nz, sp, l);
    }
    __syncthreads();

    // --- per-token top-8 (stable: ties keep lower index) ---
    if (tid < MT) {
        const float* row = Ls + tid * LS_STRIDE;
        const float NEG_INF = __int_as_float(0xff800000);
        float best[TOPK]; int bidx[TOPK];
#pragma unroll
        for (int i = 0; i < TOPK; ++i) { best[i] = NEG_INF; bidx[i] = -1; }
        for (int e = 0; e < EDIM; ++e) {
            float v = row[e];
            if (v > best[TOPK - 1]) {
                best[TOPK - 1] = v; bidx[TOPK - 1] = e;
#pragma unroll
                for (int jj = TOPK - 1; jj > 0; --jj) {
                    if (best[jj] > best[jj - 1]) {
                        float tv = best[jj]; best[jj] = best[jj - 1]; best[jj - 1] = tv;
                        int ti = bidx[jj]; bidx[jj] = bidx[jj - 1]; bidx[jj - 1] = ti;
                    }
                }
            }
        }
        float mx = best[0], ssum = 0.0f;
        unsigned long long mask = 0ULL;
#pragma unroll
        for (int i = 0; i < TOPK; ++i) { ssum += expf(best[i] - mx); mask |= 1ULL << bidx[i]; }
        s_max[tid] = mx;
        s_inv[tid] = 1.0f / ssum;
        s_msk[tid] = mask;
        if (write_indices) {
            float* oi = out_indices + (size_t)(tokBase + tid) * TOPK;
#pragma unroll
            for (int i = 0; i < TOPK; ++i) oi[i] = (float)bidx[i];
        }
    }
    __syncthreads();

    // --- sparse softmax write (coalesced) ---
    for (int i = tid; i < MT * EDIM; i += 256) {
        const int t = i >> 6, e = i & 63;
        float r = 0.0f;
        if ((s_msk[t] >> e) & 1ULL)
            r = expf(Ls[t * LS_STRIDE + e] - s_max[t]) * s_inv[t];
        out_router[(size_t)(tokBase + t) * EDIM + e] = r;
    }
}

extern "C" void kernel_launch(void* const* d_in, const int* in_sizes, int n_in,
                              void* d_out, int out_size) {
    const float* x  = (const float*)d_in[0];   // (4,4096,2048)
    const float* wr = (const float*)d_in[1];   // (64,2048)
    const float* wn = (const float*)d_in[2];   // (64,2048)
    const float* nz = (const float*)d_in[3];   // (4,4096,64)
    float* out = (float*)d_out;

    const int M = in_sizes[0] / CDIM;          // 16384 tokens
    const int write_idx = (out_size >= M * EDIM + M * TOPK) ? 1 : 0;
    float* out_idx = out + (size_t)M * EDIM;

    prep_w_kernel<<<128, 256>>>(wr, wn);
    cudaFuncSetAttribute(router_mma_kernel,
                         cudaFuncAttributeMaxDynamicSharedMemorySize, SMEM_DYN);
    router_mma_kernel<<<M / MT, 256, SMEM_DYN>>>(x, nz, out, out_idx, write_idx);
}

// round 7
// speedup vs baseline: 1.1930x; 1.1930x over previous
#include <cuda_runtime.h>
#include <cuda_fp16.h>
#include <cstdint>

#define CDIM   2048
#define EDIM   64
#define NTOT   128          // 64 route + 64 noise outputs fused in N
#define TOPK   8
#define MT     128          // tokens per CTA
#define KC     32           // K per chunk
#define NCHUNK (CDIM / KC)  // 64
#define NTHR   512

// operand scaling to keep fp16 residuals out of subnormal range
#define XSCALE   16.0f
#define WSCALE   64.0f
#define DESCALE  (1.0f / (XSCALE * WSCALE))

// smem tile rows: 32 halves (64B) padded to 80B (conflict-free ldmatrix)
#define AROW        80
#define TILE_B      (128 * AROW)        // 10240 B per operand tile (A or B, hi or lo)
#define STAGE_B     (4 * TILE_B)        // Ahi, Alo, Bhi, Blo = 40960 B
#define SMEM_DYN    (2 * STAGE_B)       // 81920 B (reused as Ls in epilogue)
#define LS_STRIDE   129                 // 128*129*4 = 66048 B < SMEM_DYN

static __device__ __forceinline__ uint32_t smem_u32(const void* p) {
    uint32_t a;
    asm("{ .reg .u64 t; cvta.to.shared.u64 t, %1; cvt.u32.u64 %0, t; }" : "=r"(a) : "l"(p));
    return a;
}
static __device__ __forceinline__ void ldm_x4(uint32_t& r0, uint32_t& r1, uint32_t& r2,
                                              uint32_t& r3, uint32_t addr) {
    asm volatile("ldmatrix.sync.aligned.m8n8.x4.shared.b16 {%0,%1,%2,%3}, [%4];"
                 : "=r"(r0), "=r"(r1), "=r"(r2), "=r"(r3) : "r"(addr));
}
static __device__ __forceinline__ void mma16816(float* c, const uint32_t* a,
                                                const uint32_t* b) {
    asm volatile(
        "mma.sync.aligned.m16n8k16.row.col.f32.f16.f16.f32 "
        "{%0,%1,%2,%3}, {%4,%5,%6,%7}, {%8,%9}, {%0,%1,%2,%3};"
        : "+f"(c[0]), "+f"(c[1]), "+f"(c[2]), "+f"(c[3])
        : "r"(a[0]), "r"(a[1]), "r"(a[2]), "r"(a[3]), "r"(b[0]), "r"(b[1]));
}
static __device__ __forceinline__ uint32_t pack2h(__half a, __half b) {
    __half2 h = __halves2half2(a, b);
    return *reinterpret_cast<uint32_t*>(&h);
}
// Scale, then split into hi/lo fp16 quads and store 8B each.
static __device__ __forceinline__ void cvt_store(char* hi, char* lo, uint32_t off,
                                                 float4 v, float scale) {
    v.x *= scale; v.y *= scale; v.z *= scale; v.w *= scale;
    __half h0 = __float2half_rn(v.x), h1 = __float2half_rn(v.y);
    __half h2 = __float2half_rn(v.z), h3 = __float2half_rn(v.w);
    float r0 = v.x - __half2float(h0), r1 = v.y - __half2float(h1);
    float r2 = v.z - __half2float(h2), r3 = v.w - __half2float(h3);
    uint2 ph = make_uint2(pack2h(h0, h1), pack2h(h2, h3));
    uint2 pl = make_uint2(pack2h(__float2half_rn(r0), __float2half_rn(r1)),
                          pack2h(__float2half_rn(r2), __float2half_rn(r3)));
    *(uint2*)(hi + off) = ph;
    *(uint2*)(lo + off) = pl;
}

__global__ __launch_bounds__(NTHR, 1)
void router_mma_kernel(
    const float* __restrict__ x, const float* __restrict__ w_route,
    const float* __restrict__ w_noise, const float* __restrict__ noise,
    float* __restrict__ out_router, float* __restrict__ out_indices, int write_indices)
{
    extern __shared__ __align__(16) char smem[];
    __shared__ float s_max[MT];
    __shared__ float s_inv[MT];
    __shared__ unsigned long long s_msk[MT];

    const uint32_t sb = smem_u32(smem);
    const int tid = threadIdx.x;
    const int wid = tid >> 5, lane = tid & 31;
    const int wr_ = wid >> 2;            // warp row: tokens [32*wr_, +32)
    const int wc_ = wid & 3;             // warp col: outputs [32*wc_, +32)
    const int tokBase = blockIdx.x * MT;

    // fill mapping: idx = tid + 512*it (it 0..1) -> row = idx>>3 (0..127), q = idx&7
    const int f_row = tid >> 3;          // 0..63 for it=0; +64 for it=1
    const int f_q   = tid & 7;

    // ldmatrix lane-address components
    const int j = lane >> 3, rr = lane & 7;
    const int a_off0 = (32 * wr_ + (j & 1) * 8 + rr) * AROW + (j >> 1) * 16;  // + mt*16*80 + ks*32
    const int b_off0 = (32 * wc_ + (j >> 1) * 8 + rr) * AROW + (j & 1) * 16;  // + p*16*80 + ks*32

    float acc[2][4][4];
#pragma unroll
    for (int mt = 0; mt < 2; ++mt)
#pragma unroll
        for (int nt = 0; nt < 4; ++nt)
#pragma unroll
            for (int k = 0; k < 4; ++k) acc[mt][nt][k] = 0.0f;

    // ---- prologue: load chunk 0 and publish to stage 0 ----
    float4 areg[2], breg[2];
#pragma unroll
    for (int it = 0; it < 2; ++it) {
        const int row = f_row + it * 64;
        areg[it] = *(const float4*)(x + (size_t)(tokBase + row) * CDIM + f_q * 4);
        const float* wsrc = (row < EDIM) ? (w_route + (size_t)row * CDIM)
                                         : (w_noise + (size_t)(row - EDIM) * CDIM);
        breg[it] = *(const float4*)(wsrc + f_q * 4);
    }
#pragma unroll
    for (int it = 0; it < 2; ++it) {
        const uint32_t off = (uint32_t)(f_row + it * 64) * AROW + f_q * 8;
        cvt_store(smem, smem + TILE_B, off, areg[it], XSCALE);
        cvt_store(smem + 2 * TILE_B, smem + 3 * TILE_B, off, breg[it], WSCALE);
    }
    __syncthreads();

    // ---- mainloop: prefetch(c+1) || compute(c) || publish(c+1), one sync ----
    for (int c = 0; c < NCHUNK; ++c) {
        const int s = c & 1;
        const int has_next = (c + 1 < NCHUNK);
        if (has_next) {
            const int k0 = (c + 1) * KC;
#pragma unroll
            for (int it = 0; it < 2; ++it) {
                const int row = f_row + it * 64;
                areg[it] = *(const float4*)(x + (size_t)(tokBase + row) * CDIM + k0 + f_q * 4);
                const float* wsrc = (row < EDIM) ? (w_route + (size_t)row * CDIM)
                                                 : (w_noise + (size_t)(row - EDIM) * CDIM);
                breg[it] = *(const float4*)(wsrc + k0 + f_q * 4);
            }
        }

        // compute chunk c from stage s
        const uint32_t ah_b = sb + s * STAGE_B;
        const uint32_t al_b = ah_b + TILE_B;
        const uint32_t bh_b = ah_b + 2 * TILE_B;
        const uint32_t bl_b = ah_b + 3 * TILE_B;
#pragma unroll
        for (int ks = 0; ks < 2; ++ks) {
            uint32_t a_hi[2][4], a_lo[2][4];
#pragma unroll
            for (int mt = 0; mt < 2; ++mt) {
                const uint32_t ao = a_off0 + mt * (16 * AROW) + ks * 32;
                ldm_x4(a_hi[mt][0], a_hi[mt][1], a_hi[mt][2], a_hi[mt][3], ah_b + ao);
                ldm_x4(a_lo[mt][0], a_lo[mt][1], a_lo[mt][2], a_lo[mt][3], al_b + ao);
            }
            uint32_t b_hi[4][2], b_lo[4][2];
#pragma unroll
            for (int p = 0; p < 2; ++p) {
                const uint32_t bo = b_off0 + p * (16 * AROW) + ks * 32;
                ldm_x4(b_hi[2 * p][0], b_hi[2 * p][1], b_hi[2 * p + 1][0], b_hi[2 * p + 1][1],
                       bh_b + bo);
                ldm_x4(b_lo[2 * p][0], b_lo[2 * p][1], b_lo[2 * p + 1][0], b_lo[2 * p + 1][1],
                       bl_b + bo);
            }
#pragma unroll
            for (int mt = 0; mt < 2; ++mt)
#pragma unroll
                for (int nt = 0; nt < 4; ++nt) {
                    mma16816(acc[mt][nt], a_hi[mt], b_hi[nt]);
                    mma16816(acc[mt][nt], a_hi[mt], b_lo[nt]);
                    mma16816(acc[mt][nt], a_lo[mt], b_hi[nt]);
                }
        }

        // publish chunk c+1 into the other stage
        if (has_next) {
            char* Ah = smem + (1 - s) * STAGE_B;
#pragma unroll
            for (int it = 0; it < 2; ++it) {
                const uint32_t off = (uint32_t)(f_row + it * 64) * AROW + f_q * 8;
                cvt_store(Ah, Ah + TILE_B, off, areg[it], XSCALE);
                cvt_store(Ah + 2 * TILE_B, Ah + 3 * TILE_B, off, breg[it], WSCALE);
            }
        }
        __syncthreads();
    }

    // --- accumulators -> Ls[token][output] (smem reuse, descaled) ---
    float* Ls = (float*)smem;
    {
        const int r0 = 32 * wr_ + (lane >> 2);
        const int c0 = 32 * wc_ + 2 * (lane & 3);
#pragma unroll
        for (int mt = 0; mt < 2; ++mt)
#pragma unroll
            for (int nt = 0; nt < 4; ++nt) {
                const int row = r0 + 16 * mt;
                const int col = c0 + 8 * nt;
                Ls[row * LS_STRIDE + col]           = acc[mt][nt][0] * DESCALE;
                Ls[row * LS_STRIDE + col + 1]       = acc[mt][nt][1] * DESCALE;
                Ls[(row + 8) * LS_STRIDE + col]     = acc[mt][nt][2] * DESCALE;
                Ls[(row + 8) * LS_STRIDE + col + 1] = acc[mt][nt][3] * DESCALE;
            }
    }
    __syncthreads();

    // --- noisy = logit + noise * softplus(noise_logit) ---
    for (int i = tid; i < MT * EDIM; i += NTHR) {
        const int t = i >> 6, e = i & 63;
        float l  = Ls[t * LS_STRIDE + e];
        float nl = Ls[t * LS_STRIDE + EDIM + e];
        float nz = noise[(size_t)(tokBase + t) * EDIM + e];
        float sp = fmaxf(nl, 0.0f) + log1pf(expf(-fabsf(nl)));
        Ls[t * LS_STRIDE + e] = fmaf(nz, sp, l);
    }
    __syncthreads();

    // --- per-token top-8 (stable: ties keep lower index) ---
    if (tid < MT) {
        const float* row = Ls + tid * LS_STRIDE;
        const float NEG_INF = __int_as_float(0xff800000);
        float best[TOPK]; int bidx[TOPK];
#pragma unroll
        for (int i = 0; i < TOPK; ++i) { best[i] = NEG_INF; bidx[i] = -1; }
        for (int e = 0; e < EDIM; ++e) {
            float v = row[e];
            if (v > best[TOPK - 1]) {
                best[TOPK - 1] = v; bidx[TOPK - 1] = e;
#pragma unroll
                for (int jj = TOPK - 1; jj > 0; --jj) {
                    if (best[jj] > best[jj - 1]) {
                        float tv = best[jj]; best[jj] = best[jj - 1]; best[jj - 1] = tv;
                        int ti = bidx[jj]; bidx[jj] = bidx[jj - 1]; bidx[jj - 1] = ti;
                    }
                }
            }
        }
        float mx = best[0], ssum = 0.0f;
        unsigned long long mask = 0ULL;
#pragma unroll
        for (int i = 0; i < TOPK; ++i) { ssum += expf(best[i] - mx); mask |= 1ULL << bidx[i]; }
        s_max[tid] = mx;
        s_inv[tid] = 1.0f / ssum;
        s_msk[tid] = mask;
        if (write_indices) {
            float* oi = out_indices + (size_t)(tokBase + tid) * TOPK;
#pragma unroll
            for (int i = 0; i < TOPK; ++i) oi[i] = (float)bidx[i];
        }
    }
    __syncthreads();

    // --- sparse softmax write (coalesced) ---
    for (int i = tid; i < MT * EDIM; i += NTHR) {
        const int t = i >> 6, e = i & 63;
        float r = 0.0f;
        if ((s_msk[t] >> e) & 1ULL)
            r = expf(Ls[t * LS_STRIDE + e] - s_max[t]) * s_inv[t];
        out_router[(size_t)(tokBase + t) * EDIM + e] = r;
    }
}

extern "C" void kernel_launch(void* const* d_in, const int* in_sizes, int n_in,
                              void* d_out, int out_size) {
    const float* x  = (const float*)d_in[0];   // (4,4096,2048)
    const float* wr = (const float*)d_in[1];   // (64,2048)
    const float* wn = (const float*)d_in[2];   // (64,2048)
    const float* nz = (const float*)d_in[3];   // (4,4096,64)
    float* out = (float*)d_out;

    const int M = in_sizes[0] / CDIM;          // 16384 tokens
    const int write_idx = (out_size >= M * EDIM + M * TOPK) ? 1 : 0;
    float* out_idx = out + (size_t)M * EDIM;

    cudaFuncSetAttribute(router_mma_kernel,
                         cudaFuncAttributeMaxDynamicSharedMemorySize, SMEM_DYN);
    router_mma_kernel<<<M / MT, NTHR, SMEM_DYN>>>(x, wr, wn, nz, out, out_idx, write_idx);
}

// round 8
// speedup vs baseline: 1.2471x; 1.0453x over previous
#include <cuda_runtime.h>
#include <cuda_fp16.h>
#include <cstdint>

#define CDIM   2048
#define EDIM   64
#define NTOT   128          // 64 route + 64 noise outputs fused in N
#define TOPK   8
#define MT     128          // tokens per CTA
#define KC     32           // K per chunk
#define NCHUNK (CDIM / KC)  // 64
#define NTHR   512

// operand scaling to keep fp16 residuals out of subnormal range
#define XSCALE   16.0f
#define WSCALE   64.0f
#define DESCALE  (1.0f / (XSCALE * WSCALE))

// smem tile rows: 32 halves (64B) padded to 80B (conflict-free ldmatrix)
#define AROW        80
#define TILE_B      (128 * AROW)        // 10240 B per operand tile (A or B, hi or lo)
#define STAGE_B     (4 * TILE_B)        // Ahi, Alo, Bhi, Blo = 40960 B
#define SMEM_DYN    (2 * STAGE_B)       // 81920 B (reused as Ls in epilogue)
#define LS_STRIDE   129                 // 128*129*4 = 66048 B < SMEM_DYN

static __device__ __forceinline__ uint32_t smem_u32(const void* p) {
    uint32_t a;
    asm("{ .reg .u64 t; cvta.to.shared.u64 t, %1; cvt.u32.u64 %0, t; }" : "=r"(a) : "l"(p));
    return a;
}
static __device__ __forceinline__ void ldm_x4(uint32_t& r0, uint32_t& r1, uint32_t& r2,
                                              uint32_t& r3, uint32_t addr) {
    asm volatile("ldmatrix.sync.aligned.m8n8.x4.shared.b16 {%0,%1,%2,%3}, [%4];"
                 : "=r"(r0), "=r"(r1), "=r"(r2), "=r"(r3) : "r"(addr));
}
static __device__ __forceinline__ void mma16816(float* c, const uint32_t* a,
                                                const uint32_t* b) {
    asm volatile(
        "mma.sync.aligned.m16n8k16.row.col.f32.f16.f16.f32 "
        "{%0,%1,%2,%3}, {%4,%5,%6,%7}, {%8,%9}, {%0,%1,%2,%3};"
        : "+f"(c[0]), "+f"(c[1]), "+f"(c[2]), "+f"(c[3])
        : "r"(a[0]), "r"(a[1]), "r"(a[2]), "r"(a[3]), "r"(b[0]), "r"(b[1]));
}
static __device__ __forceinline__ uint32_t pack2h(__half a, __half b) {
    __half2 h = __halves2half2(a, b);
    return *reinterpret_cast<uint32_t*>(&h);
}
// Scale, then split into hi/lo fp16 quads and store 8B each.
static __device__ __forceinline__ void cvt_store(char* hi, char* lo, uint32_t off,
                                                 float4 v, float scale) {
    v.x *= scale; v.y *= scale; v.z *= scale; v.w *= scale;
    __half h0 = __float2half_rn(v.x), h1 = __float2half_rn(v.y);
    __half h2 = __float2half_rn(v.z), h3 = __float2half_rn(v.w);
    float r0 = v.x - __half2float(h0), r1 = v.y - __half2float(h1);
    float r2 = v.z - __half2float(h2), r3 = v.w - __half2float(h3);
    uint2 ph = make_uint2(pack2h(h0, h1), pack2h(h2, h3));
    uint2 pl = make_uint2(pack2h(__float2half_rn(r0), __float2half_rn(r1)),
                          pack2h(__float2half_rn(r2), __float2half_rn(r3)));
    *(uint2*)(hi + off) = ph;
    *(uint2*)(lo + off) = pl;
}

__global__ __launch_bounds__(NTHR, 1)
void router_mma_kernel(
    const float* __restrict__ x, const float* __restrict__ w_route,
    const float* __restrict__ w_noise, const float* __restrict__ noise,
    float* __restrict__ out_router, float* __restrict__ out_indices, int write_indices)
{
    extern __shared__ __align__(16) char smem[];
    __shared__ float s_max[MT];
    __shared__ float s_inv[MT];
    __shared__ unsigned long long s_msk[MT];

    const uint32_t sb = smem_u32(smem);
    const int tid = threadIdx.x;
    const int wid = tid >> 5, lane = tid & 31;
    const int wr_ = wid >> 2;            // warp row: tokens [32*wr_, +32)
    const int wc_ = wid & 3;             // warp col: outputs [32*wc_, +32)
    const int tokBase = blockIdx.x * MT;

    // fill mapping: idx = tid + 512*it (it 0..1) -> row = idx>>3 (0..127), q = idx&7
    const int f_row = tid >> 3;
    const int f_q   = tid & 7;

    // ldmatrix lane-address components
    const int j = lane >> 3, rr = lane & 7;
    const int a_off0 = (32 * wr_ + (j & 1) * 8 + rr) * AROW + (j >> 1) * 16;  // + mt*16*80 + ks*32
    const int b_off0 = (32 * wc_ + (j >> 1) * 8 + rr) * AROW + (j & 1) * 16;  // + p*16*80 + ks*32

    float acc[2][4][4];
#pragma unroll
    for (int mt = 0; mt < 2; ++mt)
#pragma unroll
        for (int nt = 0; nt < 4; ++nt)
#pragma unroll
            for (int k = 0; k < 4; ++k) acc[mt][nt][k] = 0.0f;

    // double-buffered hi fragments; lo fragments loaded just-in-time
    uint32_t ahi[2][2][4];   // [buf][mt][r]
    uint32_t bhi[2][4][2];   // [buf][nt][r]

    // ---- prologue: load chunk 0 and publish to stage 0 ----
    float4 areg[2], breg[2];
#pragma unroll
    for (int it = 0; it < 2; ++it) {
        const int row = f_row + it * 64;
        areg[it] = *(const float4*)(x + (size_t)(tokBase + row) * CDIM + f_q * 4);
        const float* wsrc = (row < EDIM) ? (w_route + (size_t)row * CDIM)
                                         : (w_noise + (size_t)(row - EDIM) * CDIM);
        breg[it] = *(const float4*)(wsrc + f_q * 4);
    }
#pragma unroll
    for (int it = 0; it < 2; ++it) {
        const uint32_t off = (uint32_t)(f_row + it * 64) * AROW + f_q * 8;
        cvt_store(smem, smem + TILE_B, off, areg[it], XSCALE);
        cvt_store(smem + 2 * TILE_B, smem + 3 * TILE_B, off, breg[it], WSCALE);
    }
    __syncthreads();

    // preload hi frags of (stage 0, ks 0) into buf 0
    {
        const uint32_t ah_b = sb, bh_b = sb + 2 * TILE_B;
#pragma unroll
        for (int mt = 0; mt < 2; ++mt)
            ldm_x4(ahi[0][mt][0], ahi[0][mt][1], ahi[0][mt][2], ahi[0][mt][3],
                   ah_b + a_off0 + mt * (16 * AROW));
#pragma unroll
        for (int p = 0; p < 2; ++p)
            ldm_x4(bhi[0][2 * p][0], bhi[0][2 * p][1], bhi[0][2 * p + 1][0],
                   bhi[0][2 * p + 1][1], bh_b + b_off0 + p * (16 * AROW));
    }

    // ---- mainloop ----
    for (int c = 0; c < NCHUNK; ++c) {
        const int s = c & 1;
        const int has_next = (c + 1 < NCHUNK);

        // global prefetch for chunk c+1
        if (has_next) {
            const int k0 = (c + 1) * KC;
#pragma unroll
            for (int it = 0; it < 2; ++it) {
                const int row = f_row + it * 64;
                areg[it] = *(const float4*)(x + (size_t)(tokBase + row) * CDIM + k0 + f_q * 4);
                const float* wsrc = (row < EDIM) ? (w_route + (size_t)row * CDIM)
                                                 : (w_noise + (size_t)(row - EDIM) * CDIM);
                breg[it] = *(const float4*)(wsrc + k0 + f_q * 4);
            }
        }

        const uint32_t ah_b = sb + s * STAGE_B;
        const uint32_t al_b = ah_b + TILE_B;
        const uint32_t bh_b = ah_b + 2 * TILE_B;
        const uint32_t bl_b = ah_b + 3 * TILE_B;

#pragma unroll
        for (int ks = 0; ks < 2; ++ks) {
            const int cur = ks;          // buf holding this ks' hi frags
            // just-in-time lo frags for this ks
            uint32_t alo[2][4], blo[4][2];
#pragma unroll
            for (int mt = 0; mt < 2; ++mt)
                ldm_x4(alo[mt][0], alo[mt][1], alo[mt][2], alo[mt][3],
                       al_b + a_off0 + mt * (16 * AROW) + ks * 32);
#pragma unroll
            for (int p = 0; p < 2; ++p)
                ldm_x4(blo[2 * p][0], blo[2 * p][1], blo[2 * p + 1][0], blo[2 * p + 1][1],
                       bl_b + b_off0 + p * (16 * AROW) + ks * 32);
            // preload hi frags for ks=1 into buf 1 while ks=0's MMAs run
            if (ks == 0) {
#pragma unroll
                for (int mt = 0; mt < 2; ++mt)
                    ldm_x4(ahi[1][mt][0], ahi[1][mt][1], ahi[1][mt][2], ahi[1][mt][3],
                           ah_b + a_off0 + mt * (16 * AROW) + 32);
#pragma unroll
                for (int p = 0; p < 2; ++p)
                    ldm_x4(bhi[1][2 * p][0], bhi[1][2 * p][1], bhi[1][2 * p + 1][0],
                           bhi[1][2 * p + 1][1], bh_b + b_off0 + p * (16 * AROW) + 32);
            }
            // MMAs grouped by term; per-acc order hihi->hilo->lohi (bitwise == R7)
#pragma unroll
            for (int mt = 0; mt < 2; ++mt)
#pragma unroll
                for (int nt = 0; nt < 4; ++nt)
                    mma16816(acc[mt][nt], ahi[cur][mt], bhi[cur][nt]);
#pragma unroll
            for (int mt = 0; mt < 2; ++mt)
#pragma unroll
                for (int nt = 0; nt < 4; ++nt)
                    mma16816(acc[mt][nt], ahi[cur][mt], blo[nt]);
#pragma unroll
            for (int mt = 0; mt < 2; ++mt)
#pragma unroll
                for (int nt = 0; nt < 4; ++nt)
                    mma16816(acc[mt][nt], alo[mt], bhi[cur][nt]);
        }

        // publish chunk c+1 into the other stage
        if (has_next) {
            char* Ah = smem + (1 - s) * STAGE_B;
#pragma unroll
            for (int it = 0; it < 2; ++it) {
                const uint32_t off = (uint32_t)(f_row + it * 64) * AROW + f_q * 8;
                cvt_store(Ah, Ah + TILE_B, off, areg[it], XSCALE);
                cvt_store(Ah + 2 * TILE_B, Ah + 3 * TILE_B, off, breg[it], WSCALE);
            }
        }
        __syncthreads();

        // preload hi frags of next chunk's ks0 into buf 0
        if (has_next) {
            const uint32_t nah = sb + (1 - s) * STAGE_B;
            const uint32_t nbh = nah + 2 * TILE_B;
#pragma unroll
            for (int mt = 0; mt < 2; ++mt)
                ldm_x4(ahi[0][mt][0], ahi[0][mt][1], ahi[0][mt][2], ahi[0][mt][3],
                       nah + a_off0 + mt * (16 * AROW));
#pragma unroll
            for (int p = 0; p < 2; ++p)
                ldm_x4(bhi[0][2 * p][0], bhi[0][2 * p][1], bhi[0][2 * p + 1][0],
                       bhi[0][2 * p + 1][1], nbh + b_off0 + p * (16 * AROW));
        }
    }

    // --- accumulators -> Ls[token][output] (smem reuse, descaled) ---
    float* Ls = (float*)smem;
    {
        const int r0 = 32 * wr_ + (lane >> 2);
        const int c0 = 32 * wc_ + 2 * (lane & 3);
#pragma unroll
        for (int mt = 0; mt < 2; ++mt)
#pragma unroll
            for (int nt = 0; nt < 4; ++nt) {
                const int row = r0 + 16 * mt;
                const int col = c0 + 8 * nt;
                Ls[row * LS_STRIDE + col]           = acc[mt][nt][0] * DESCALE;
                Ls[row * LS_STRIDE + col + 1]       = acc[mt][nt][1] * DESCALE;
                Ls[(row + 8) * LS_STRIDE + col]     = acc[mt][nt][2] * DESCALE;
                Ls[(row + 8) * LS_STRIDE + col + 1] = acc[mt][nt][3] * DESCALE;
            }
    }
    __syncthreads();

    // --- noisy = logit + noise * softplus(noise_logit) ---
    for (int i = tid; i < MT * EDIM; i += NTHR) {
        const int t = i >> 6, e = i & 63;
        float l  = Ls[t * LS_STRIDE + e];
        float nl = Ls[t * LS_STRIDE + EDIM + e];
        float nz = noise[(size_t)(tokBase + t) * EDIM + e];
        float sp = fmaxf(nl, 0.0f) + log1pf(expf(-fabsf(nl)));
        Ls[t * LS_STRIDE + e] = fmaf(nz, sp, l);
    }
    __syncthreads();

    // --- per-token top-8 (stable: ties keep lower index) ---
    if (tid < MT) {
        const float* row = Ls + tid * LS_STRIDE;
        const float NEG_INF = __int_as_float(0xff800000);
        float best[TOPK]; int bidx[TOPK];
#pragma unroll
        for (int i = 0; i < TOPK; ++i) { best[i] = NEG_INF; bidx[i] = -1; }
        for (int e = 0; e < EDIM; ++e) {
            float v = row[e];
            if (v > best[TOPK - 1]) {
                best[TOPK - 1] = v; bidx[TOPK - 1] = e;
#pragma unroll
                for (int jj = TOPK - 1; jj > 0; --jj) {
                    if (best[jj] > best[jj - 1]) {
                        float tv = best[jj]; best[jj] = best[jj - 1]; best[jj - 1] = tv;
                        int ti = bidx[jj]; bidx[jj] = bidx[jj - 1]; bidx[jj - 1] = ti;
                    }
                }
            }
        }
        float mx = best[0], ssum = 0.0f;
        unsigned long long mask = 0ULL;
#pragma unroll
        for (int i = 0; i < TOPK; ++i) { ssum += expf(best[i] - mx); mask |= 1ULL << bidx[i]; }
        s_max[tid] = mx;
        s_inv[tid] = 1.0f / ssum;
        s_msk[tid] = mask;
        if (write_indices) {
            float* oi = out_indices + (size_t)(tokBase + tid) * TOPK;
#pragma unroll
            for (int i = 0; i < TOPK; ++i) oi[i] = (float)bidx[i];
        }
    }
    __syncthreads();

    // --- sparse softmax write (coalesced) ---
    for (int i = tid; i < MT * EDIM; i += NTHR) {
        const int t = i >> 6, e = i & 63;
        float r = 0.0f;
        if ((s_msk[t] >> e) & 1ULL)
            r = expf(Ls[t * LS_STRIDE + e] - s_max[t]) * s_inv[t];
        out_router[(size_t)(tokBase + t) * EDIM + e] = r;
    }
}

extern "C" void kernel_launch(void* const* d_in, const int* in_sizes, int n_in,
                              void* d_out, int out_size) {
    const float* x  = (const float*)d_in[0];   // (4,4096,2048)
    const float* wr = (const float*)d_in[1];   // (64,2048)
    const float* wn = (const float*)d_in[2];   // (64,2048)
    const float* nz = (const float*)d_in[3];   // (4,4096,64)
    float* out = (float*)d_out;

    const int M = in_sizes[0] / CDIM;          // 16384 tokens
    const int write_idx = (out_size >= M * EDIM + M * TOPK) ? 1 : 0;
    float* out_idx = out + (size_t)M * EDIM;

    cudaFuncSetAttribute(router_mma_kernel,
                         cudaFuncAttributeMaxDynamicSharedMemorySize, SMEM_DYN);
    router_mma_kernel<<<M / MT, NTHR, SMEM_DYN>>>(x, wr, wn, nz, out, out_idx, write_idx);
}

// round 9
// speedup vs baseline: 1.3317x; 1.0678x over previous
#include <cuda_runtime.h>
#include <cuda_fp16.h>
#include <cstdint>

#define CDIM   2048
#define EDIM   64
#define NTOT   128          // 64 route + 64 noise outputs fused in N
#define TOPK   8
#define MT     128          // tokens per CTA
#define KC     64           // K per chunk (4 ks-steps of 16)
#define NCHUNK (CDIM / KC)  // 32
#define NTHR   512

// operand scaling to keep fp16 residuals out of subnormal range
#define XSCALE   16.0f
#define WSCALE   64.0f
#define DESCALE  (1.0f / (XSCALE * WSCALE))

// smem tile rows: 64 halves (128B) padded to 144B (conflict-free ldmatrix)
#define AROW        144
#define TILE_B      (128 * AROW)        // 18432 B per operand tile (A or B, hi or lo)
#define STAGE_B     (4 * TILE_B)        // Ahi, Alo, Bhi, Blo = 73728 B
#define SMEM_DYN    (2 * STAGE_B)       // 147456 B (reused as Ls in epilogue)
#define LS_STRIDE   129                 // 128*129*4 = 66048 B < SMEM_DYN

static __device__ __forceinline__ uint32_t smem_u32(const void* p) {
    uint32_t a;
    asm("{ .reg .u64 t; cvta.to.shared.u64 t, %1; cvt.u32.u64 %0, t; }" : "=r"(a) : "l"(p));
    return a;
}
static __device__ __forceinline__ void ldm_x4(uint32_t& r0, uint32_t& r1, uint32_t& r2,
                                              uint32_t& r3, uint32_t addr) {
    asm volatile("ldmatrix.sync.aligned.m8n8.x4.shared.b16 {%0,%1,%2,%3}, [%4];"
                 : "=r"(r0), "=r"(r1), "=r"(r2), "=r"(r3) : "r"(addr));
}
static __device__ __forceinline__ void mma16816(float* c, const uint32_t* a,
                                                const uint32_t* b) {
    asm volatile(
        "mma.sync.aligned.m16n8k16.row.col.f32.f16.f16.f32 "
        "{%0,%1,%2,%3}, {%4,%5,%6,%7}, {%8,%9}, {%0,%1,%2,%3};"
        : "+f"(c[0]), "+f"(c[1]), "+f"(c[2]), "+f"(c[3])
        : "r"(a[0]), "r"(a[1]), "r"(a[2]), "r"(a[3]), "r"(b[0]), "r"(b[1]));
}
static __device__ __forceinline__ uint32_t pack2h(__half a, __half b) {
    __half2 h = __halves2half2(a, b);
    return *reinterpret_cast<uint32_t*>(&h);
}
// Scale, then split into hi/lo fp16 quads and store 8B each.
static __device__ __forceinline__ void cvt_store(char* hi, char* lo, uint32_t off,
                                                 float4 v, float scale) {
    v.x *= scale; v.y *= scale; v.z *= scale; v.w *= scale;
    __half h0 = __float2half_rn(v.x), h1 = __float2half_rn(v.y);
    __half h2 = __float2half_rn(v.z), h3 = __float2half_rn(v.w);
    float r0 = v.x - __half2float(h0), r1 = v.y - __half2float(h1);
    float r2 = v.z - __half2float(h2), r3 = v.w - __half2float(h3);
    uint2 ph = make_uint2(pack2h(h0, h1), pack2h(h2, h3));
    uint2 pl = make_uint2(pack2h(__float2half_rn(r0), __float2half_rn(r1)),
                          pack2h(__float2half_rn(r2), __float2half_rn(r3)));
    *(uint2*)(hi + off) = ph;
    *(uint2*)(lo + off) = pl;
}

__global__ __launch_bounds__(NTHR, 1)
void router_mma_kernel(
    const float* __restrict__ x, const float* __restrict__ w_route,
    const float* __restrict__ w_noise, const float* __restrict__ noise,
    float* __restrict__ out_router, float* __restrict__ out_indices, int write_indices)
{
    extern __shared__ __align__(16) char smem[];
    __shared__ float s_max[MT];
    __shared__ float s_inv[MT];
    __shared__ unsigned long long s_msk[MT];

    const uint32_t sb = smem_u32(smem);
    const int tid = threadIdx.x;
    const int wid = tid >> 5, lane = tid & 31;
    const int wr_ = wid >> 2;            // warp row: tokens [32*wr_, +32)
    const int wc_ = wid & 3;             // warp col: outputs [32*wc_, +32)
    const int tokBase = blockIdx.x * MT;

    // fill mapping (per 32-k half): idx = tid + 512*it (it 0..1) -> row, q
    const int f_row = tid >> 3;          // 0..63 ; +64 for it=1
    const int f_q   = tid & 7;           // float4 slot within 32-k half

    // ldmatrix lane-address components
    const int j = lane >> 3, rr = lane & 7;
    const int a_off0 = (32 * wr_ + (j & 1) * 8 + rr) * AROW + (j >> 1) * 16;  // + mt*16*AROW + ks*32
    const int b_off0 = (32 * wc_ + (j >> 1) * 8 + rr) * AROW + (j & 1) * 16;  // + p*16*AROW + ks*32

    float acc[2][4][4];
#pragma unroll
    for (int mt = 0; mt < 2; ++mt)
#pragma unroll
        for (int nt = 0; nt < 4; ++nt)
#pragma unroll
            for (int k = 0; k < 4; ++k) acc[mt][nt][k] = 0.0f;

    // double-buffered hi fragments; lo fragments loaded just-in-time
    uint32_t ahi[2][2][4];   // [buf][mt][r]
    uint32_t bhi[2][4][2];   // [buf][nt][r]
    float4 areg[2], breg[2];

    // ---- helpers as lambdas ----
    auto ldg_half = [&](int kbase) {
#pragma unroll
        for (int it = 0; it < 2; ++it) {
            const int row = f_row + it * 64;
            areg[it] = *(const float4*)(x + (size_t)(tokBase + row) * CDIM + kbase + f_q * 4);
            const float* wsrc = (row < EDIM) ? (w_route + (size_t)row * CDIM)
                                             : (w_noise + (size_t)(row - EDIM) * CDIM);
            breg[it] = *(const float4*)(wsrc + kbase + f_q * 4);
        }
    };
    auto publish_half = [&](char* stage, int half) {
#pragma unroll
        for (int it = 0; it < 2; ++it) {
            const uint32_t off = (uint32_t)(f_row + it * 64) * AROW + half * 64 + f_q * 8;
            cvt_store(stage, stage + TILE_B, off, areg[it], XSCALE);
            cvt_store(stage + 2 * TILE_B, stage + 3 * TILE_B, off, breg[it], WSCALE);
        }
    };
    auto load_hi = [&](int buf, uint32_t ah_b, uint32_t bh_b, int ks) {
#pragma unroll
        for (int mt = 0; mt < 2; ++mt)
            ldm_x4(ahi[buf][mt][0], ahi[buf][mt][1], ahi[buf][mt][2], ahi[buf][mt][3],
                   ah_b + a_off0 + mt * (16 * AROW) + ks * 32);
#pragma unroll
        for (int p = 0; p < 2; ++p)
            ldm_x4(bhi[buf][2 * p][0], bhi[buf][2 * p][1], bhi[buf][2 * p + 1][0],
                   bhi[buf][2 * p + 1][1], bh_b + b_off0 + p * (16 * AROW) + ks * 32);
    };

    // ---- prologue: chunk 0 -> stage 0 (both halves) ----
    ldg_half(0);  publish_half(smem, 0);
    ldg_half(32); publish_half(smem, 1);
    __syncthreads();
    load_hi(0, sb, sb + 2 * TILE_B, 0);

    // ---- mainloop: 32 chunks, one barrier each ----
    for (int c = 0; c < NCHUNK; ++c) {
        const int s = c & 1;
        const int has_next = (c + 1 < NCHUNK);
        const uint32_t ah_b = sb + s * STAGE_B;
        const uint32_t al_b = ah_b + TILE_B;
        const uint32_t bh_b = ah_b + 2 * TILE_B;
        const uint32_t bl_b = ah_b + 3 * TILE_B;
        char* nstage = smem + (1 - s) * STAGE_B;

        if (has_next) ldg_half((c + 1) * KC);           // half0 of next chunk

#pragma unroll
        for (int ks = 0; ks < 4; ++ks) {
            const int cur = ks & 1;
            // just-in-time lo frags for this ks
            uint32_t alo[2][4], blo[4][2];
#pragma unroll
            for (int mt = 0; mt < 2; ++mt)
                ldm_x4(alo[mt][0], alo[mt][1], alo[mt][2], alo[mt][3],
                       al_b + a_off0 + mt * (16 * AROW) + ks * 32);
#pragma unroll
            for (int p = 0; p < 2; ++p)
                ldm_x4(blo[2 * p][0], blo[2 * p][1], blo[2 * p + 1][0], blo[2 * p + 1][1],
                       bl_b + b_off0 + p * (16 * AROW) + ks * 32);
            // preload hi frags of ks+1 while this ks' MMAs run
            if (ks < 3) load_hi(1 - cur, ah_b, bh_b, ks + 1);

            // MMAs grouped by term; per-acc order hihi->hilo->lohi (bitwise-stable)
#pragma unroll
            for (int mt = 0; mt < 2; ++mt)
#pragma unroll
                for (int nt = 0; nt < 4; ++nt)
                    mma16816(acc[mt][nt], ahi[cur][mt], bhi[cur][nt]);
#pragma unroll
            for (int mt = 0; mt < 2; ++mt)
#pragma unroll
                for (int nt = 0; nt < 4; ++nt)
                    mma16816(acc[mt][nt], ahi[cur][mt], blo[nt]);
#pragma unroll
            for (int mt = 0; mt < 2; ++mt)
#pragma unroll
                for (int nt = 0; nt < 4; ++nt)
                    mma16816(acc[mt][nt], alo[mt], bhi[cur][nt]);

            // mid-chunk: publish half0(c+1), then fetch half1(c+1)
            if (ks == 1 && has_next) {
                publish_half(nstage, 0);
                ldg_half((c + 1) * KC + 32);
            }
        }

        if (has_next) publish_half(nstage, 1);
        __syncthreads();
        if (has_next) load_hi(0, sb + (1 - s) * STAGE_B,
                              sb + (1 - s) * STAGE_B + 2 * TILE_B, 0);
    }

    // --- accumulators -> Ls[token][output] (smem reuse, descaled) ---
    float* Ls = (float*)smem;
    {
        const int r0 = 32 * wr_ + (lane >> 2);
        const int c0 = 32 * wc_ + 2 * (lane & 3);
#pragma unroll
        for (int mt = 0; mt < 2; ++mt)
#pragma unroll
            for (int nt = 0; nt < 4; ++nt) {
                const int row = r0 + 16 * mt;
                const int col = c0 + 8 * nt;
                Ls[row * LS_STRIDE + col]           = acc[mt][nt][0] * DESCALE;
                Ls[row * LS_STRIDE + col + 1]       = acc[mt][nt][1] * DESCALE;
                Ls[(row + 8) * LS_STRIDE + col]     = acc[mt][nt][2] * DESCALE;
                Ls[(row + 8) * LS_STRIDE + col + 1] = acc[mt][nt][3] * DESCALE;
            }
    }
    __syncthreads();

    // --- noisy = logit + noise * softplus(noise_logit) ---
    for (int i = tid; i < MT * EDIM; i += NTHR) {
        const int t = i >> 6, e = i & 63;
        float l  = Ls[t * LS_STRIDE + e];
        float nl = Ls[t * LS_STRIDE + EDIM + e];
        float nz = noise[(size_t)(tokBase + t) * EDIM + e];
        float sp = fmaxf(nl, 0.0f) + log1pf(expf(-fabsf(nl)));
        Ls[t * LS_STRIDE + e] = fmaf(nz, sp, l);
    }
    __syncthreads();

    // --- per-token top-8 (stable: ties keep lower index) ---
    if (tid < MT) {
        const float* row = Ls + tid * LS_STRIDE;
        const float NEG_INF = __int_as_float(0xff800000);
        float best[TOPK]; int bidx[TOPK];
#pragma unroll
        for (int i = 0; i < TOPK; ++i) { best[i] = NEG_INF; bidx[i] = -1; }
        for (int e = 0; e < EDIM; ++e) {
            float v = row[e];
            if (v > best[TOPK - 1]) {
                best[TOPK - 1] = v; bidx[TOPK - 1] = e;
#pragma unroll
                for (int jj = TOPK - 1; jj > 0; --jj) {
                    if (best[jj] > best[jj - 1]) {
                        float tv = best[jj]; best[jj] = best[jj - 1]; best[jj - 1] = tv;
                        int ti = bidx[jj]; bidx[jj] = bidx[jj - 1]; bidx[jj - 1] = ti;
                    }
                }
            }
        }
        float mx = best[0], ssum = 0.0f;
        unsigned long long mask = 0ULL;
#pragma unroll
        for (int i = 0; i < TOPK; ++i) { ssum += expf(best[i] - mx); mask |= 1ULL << bidx[i]; }
        s_max[tid] = mx;
        s_inv[tid] = 1.0f / ssum;
        s_msk[tid] = mask;
        if (write_indices) {
            float* oi = out_indices + (size_t)(tokBase + tid) * TOPK;
#pragma unroll
            for (int i = 0; i < TOPK; ++i) oi[i] = (float)bidx[i];
        }
    }
    __syncthreads();

    // --- sparse softmax write (coalesced) ---
    for (int i = tid; i < MT * EDIM; i += NTHR) {
        const int t = i >> 6, e = i & 63;
        float r = 0.0f;
        if ((s_msk[t] >> e) & 1ULL)
            r = expf(Ls[t * LS_STRIDE + e] - s_max[t]) * s_inv[t];
        out_router[(size_t)(tokBase + t) * EDIM + e] = r;
    }
}

extern "C" void kernel_launch(void* const* d_in, const int* in_sizes, int n_in,
                              void* d_out, int out_size) {
    const float* x  = (const float*)d_in[0];   // (4,4096,2048)
    const float* wr = (const float*)d_in[1];   // (64,2048)
    const float* wn = (const float*)d_in[2];   // (64,2048)
    const float* nz = (const float*)d_in[3];   // (4,4096,64)
    float* out = (float*)d_out;

    const int M = in_sizes[0] / CDIM;          // 16384 tokens
    const int write_idx = (out_size >= M * EDIM + M * TOPK) ? 1 : 0;
    float* out_idx = out + (size_t)M * EDIM;

    cudaFuncSetAttribute(router_mma_kernel,
                         cudaFuncAttributeMaxDynamicSharedMemorySize, SMEM_DYN);
    router_mma_kernel<<<M / MT, NTHR, SMEM_DYN>>>(x, wr, wn, nz, out, out_idx, write_idx);
}